// round 17
// baseline (speedup 1.0000x reference)
#include <cuda_runtime.h>
#include <math.h>
#include <cstdint>

// Problem constants (hardcoded in reference)
#define B 32
#define D 128
#define K 512
#define C 10
#define KH 256            // half-K per cluster rank
#define NT 1024
#define NPROD 20          // (c, half) producers

// Cross-CTA state (fac2 handoff only)
__device__ float g_fac2[C][K];
__device__ __align__(16) int g_pflag[NPROD];
__device__ int g_done = 0;

__device__ __forceinline__ void st_release_gpu(int* p, int v) {
    asm volatile("st.release.gpu.global.s32 [%0], %1;" :: "l"(p), "r"(v) : "memory");
}
__device__ __forceinline__ int4 ld_volatile_v4(const int4* p) {
    int4 v;
    asm volatile("ld.volatile.global.v4.s32 {%0,%1,%2,%3}, [%4];"
                 : "=r"(v.x), "=r"(v.y), "=r"(v.z), "=r"(v.w) : "l"(p) : "memory");
    return v;
}
__device__ __forceinline__ void fence_acq_rel_gpu() {
    asm volatile("fence.acq_rel.gpu;" ::: "memory");
}
__device__ __forceinline__ uint32_t smem_u32(const void* p) {
    uint32_t a;
    asm("{ .reg .u64 t; cvta.to.shared.u64 t, %1; cvt.u32.u64 %0, t; }"
        : "=r"(a) : "l"(p));
    return a;
}
__device__ __forceinline__ uint32_t ctarank() {
    uint32_t r;
    asm("mov.u32 %0, %%cluster_ctarank;" : "=r"(r));
    return r;
}
__device__ __forceinline__ void mbar_wait_cluster_acq(uint32_t mbar, uint32_t parity) {
    asm volatile(
        "{\n\t.reg .pred p;\n\t"
        "W%=:\n\t"
        "mbarrier.try_wait.parity.acquire.cluster.shared::cta.b64 p, [%0], %1;\n\t"
        "@!p bra W%=;\n\t}"
        :: "r"(mbar), "r"(parity) : "memory");
}

// 84 CTAs (42 clusters of 2) x 1024 threads:
//   clusters 0..31 : consumer row b; rank = K-half. Each rank streams 128 KB
//                    of U (1024 L1 wavefronts), dots its half, rank1 pushes
//                    its 10 partials into rank0's smem via DSMEM + mbarrier.
//   clusters 32..41: producer class c; rank = K-half. Release-flag handoff.
__global__ __launch_bounds__(NT, 1) __cluster_dims__(2, 1, 1)
void fused_kernel(
    const float* __restrict__ x,
    const float* __restrict__ mu,
    const float* __restrict__ U,
    const float* __restrict__ V,
    float* __restrict__ out) {
    __shared__ float sx[D];
    __shared__ float part[16][KH];   // 16 d-groups x 256 (16 KB)
    __shared__ float f1s[KH];
    __shared__ float hrow[C];        // this rank's partials
    __shared__ float hrow2[C];       // peer's partials (rank 0 only)
    __shared__ __align__(8) unsigned long long mbar;

    const int t    = threadIdx.x;
    const int w    = t >> 5;
    const int lane = t & 31;
    const int g    = t >> 6;         // d-group 0..15 (8 d-rows each)
    const int tt   = t & 63;         // float4 col within the half
    const uint32_t rank = ctarank(); // = K-half
    const int clu  = blockIdx.x >> 1;

    const bool producer = (clu >= B);
    const int  row = producer ? (clu - B) : clu;      // b or c
    const float* src = producer ? (mu + row * D) : (x + row * D);
    const float* Wg  = (producer ? V : U) + rank * KH + g * 8 * K;

    // issue all W loads first — cluster.sync latency hides under them
    float4 wv[8];
#pragma unroll
    for (int i = 0; i < 8; i++)
        wv[i] = reinterpret_cast<const float4*>(Wg + i * K)[tt];

    if (t < D) sx[t] = src[t];
    if (t == 0) {
        asm volatile("mbarrier.init.shared.b64 [%0], %1;"
                     :: "r"(smem_u32(&mbar)), "r"(C) : "memory");
    }
    __syncthreads();                 // sx + mbar init done
    // cluster barrier #1 (both ranks' mbar init visible before any DSMEM use)
    asm volatile("barrier.cluster.arrive.aligned;" ::: "memory");
    asm volatile("barrier.cluster.wait.aligned;" ::: "memory");

    // ---- phase 1: this rank's factor half-row ----
    float4 acc = make_float4(0.f, 0.f, 0.f, 0.f);
    const float* sg = sx + g * 8;
#pragma unroll
    for (int i = 0; i < 8; i++) {
        const float sv = sg[i];
        acc.x = fmaf(sv, wv[i].x, acc.x);
        acc.y = fmaf(sv, wv[i].y, acc.y);
        acc.z = fmaf(sv, wv[i].z, acc.z);
        acc.w = fmaf(sv, wv[i].w, acc.w);
    }
    reinterpret_cast<float4*>(&part[g][tt * 4])[0] = acc;
    __syncthreads();

    if (producer) {
        // reduce 16 d-partials, publish fac2 half, release flag
        if (t < 64) {
            float4 r = make_float4(0.f, 0.f, 0.f, 0.f);
#pragma unroll
            for (int gg = 0; gg < 16; gg++) {
                float4 a = reinterpret_cast<const float4*>(&part[gg][t * 4])[0];
                r.x += a.x; r.y += a.y; r.z += a.z; r.w += a.w;
            }
            reinterpret_cast<float4*>(&g_fac2[row][rank * KH])[t] = r;
        }
        __syncthreads();
        if (t == 0) st_release_gpu(&g_pflag[row * 2 + rank], 1);
        // cluster barrier #2 (match consumer count), then exit
        asm volatile("barrier.cluster.arrive.aligned;" ::: "memory");
        asm volatile("barrier.cluster.wait.aligned;" ::: "memory");
        return;
    }

    // ---------------- consumer ----------------
    // warps 16..23 fold d-group partials WHILE thread 0 polls the 20 flags
    if (t == 0) {
        const int4* fp = reinterpret_cast<const int4*>(g_pflag);
        for (;;) {
            int s = 0;
#pragma unroll
            for (int j = 0; j < NPROD / 4; j++) {
                int4 f = ld_volatile_v4(fp + j);
                s += f.x + f.y + f.z + f.w;
            }
            if (s == NPROD) break;
        }
        fence_acq_rel_gpu();
    }
    if (t >= 512 && t < 512 + KH) {
        const int k = t - 512;
        float f = part[0][k];
#pragma unroll
        for (int gg = 1; gg < 16; gg++) f += part[gg][k];
        f1s[k] = f;
    }
    __syncthreads();                 // f1s ready AND fac2 visible

    // one warp per class: dot(f1s, fac2[c, rank-half]) over 256
    if (w < C) {
        const float4* fa = reinterpret_cast<const float4*>(f1s);
        const float4* fb = reinterpret_cast<const float4*>(&g_fac2[w][rank * KH]);
        float p = 0.f;
#pragma unroll
        for (int j = 0; j < 2; j++) {
            const int i4 = lane + j * 32;
            float4 a = fa[i4];
            float4 b2 = fb[i4];
            p += a.x * b2.x + a.y * b2.y + a.z * b2.z + a.w * b2.w;
        }
#pragma unroll
        for (int o = 16; o > 0; o >>= 1)
            p += __shfl_xor_sync(0xffffffffu, p, o);
        if (lane == 0) hrow[w] = p;
    }
    __syncthreads();

    if (rank == 1) {
        // push 10 partials into rank0's hrow2 via DSMEM; each storing lane
        // arrives with release (orders its own store). mbar count = 10.
        if (w == 0 && lane < C) {
            uint32_t dst, mb;
            asm("mapa.shared::cluster.u32 %0, %1, 0;" : "=r"(dst) : "r"(smem_u32(&hrow2[lane])));
            asm("mapa.shared::cluster.u32 %0, %1, 0;" : "=r"(mb)  : "r"(smem_u32(&mbar)));
            asm volatile("st.shared::cluster.f32 [%0], %1;" :: "r"(dst), "f"(hrow[lane]) : "memory");
            asm volatile("mbarrier.arrive.release.cluster.shared::cluster.b64 _, [%0];"
                         :: "r"(mb) : "memory");
        }
    } else {
        // rank 0: wait for peer partials, then parallel fast softmax
        if (w == 0) {
            mbar_wait_cluster_acq(smem_u32(&mbar), 0);
            float h = (lane < C) ? (hrow[lane] + hrow2[lane]) : -INFINITY;
            float m = h;
#pragma unroll
            for (int o = 8; o > 0; o >>= 1)
                m = fmaxf(m, __shfl_xor_sync(0xffffffffu, m, o));
            m = __shfl_sync(0xffffffffu, m, 0);
            float e = (lane < C) ? __expf(h - m) : 0.f;   // MUFU.EX2
            float se = e;
#pragma unroll
            for (int o = 8; o > 0; o >>= 1)
                se += __shfl_xor_sync(0xffffffffu, se, o);
            se = __shfl_sync(0xffffffffu, se, 0);
            const float lse = m + __logf(se);             // MUFU.LG2
            if (lane < C) out[row * C + lane] = h - lse;

            // last finisher resets flags for the next graph replay
            int last = 0;
            if (lane == 0) last = (atomicAdd(&g_done, 1) == B - 1);
            last = __shfl_sync(0xffffffffu, last, 0);
            if (last) {
                if (lane < NPROD) g_pflag[lane] = 0;
                if (lane == NPROD) g_done = 0;
            }
        }
    }

    // cluster barrier #2: rank0's smem stays live until rank1's stores landed
    asm volatile("barrier.cluster.arrive.aligned;" ::: "memory");
    asm volatile("barrier.cluster.wait.aligned;" ::: "memory");
}

extern "C" void kernel_launch(void* const* d_in, const int* in_sizes, int n_in,
                              void* d_out, int out_size) {
    const float* x  = (const float*)d_in[0];  // [32, 128]
    const float* mu = (const float*)d_in[1];  // [10, 128]
    const float* U  = (const float*)d_in[2];  // [128, 512]
    const float* V  = (const float*)d_in[3];  // [128, 512]
    float* out = (float*)d_out;               // [32, 10]

    fused_kernel<<<2 * (B + C), NT>>>(x, mu, U, V, out);
}